// round 4
// baseline (speedup 1.0000x reference)
#include <cuda_runtime.h>
#include <cstdint>

#define SEQ  4096
#define DIN  768
#define DOUT 768

// Scratch (allocation-free: __device__ globals).
__device__ float g_Q[SEQ * DOUT];
__device__ float g_K[SEQ * DOUT];
__device__ float g_V[SEQ * DOUT];
__device__ float g_S[(size_t)SEQ * SEQ];

// ---------------------------------------------------------------------------
// helpers
// ---------------------------------------------------------------------------
__device__ __forceinline__ uint32_t f2tf32(float f) {
    uint32_t r;
    asm("cvt.rna.tf32.f32 %0, %1;" : "=r"(r) : "f"(f));
    return r;
}

__device__ __forceinline__ void ldsm4(uint32_t r[4], uint32_t saddr) {
    asm volatile("ldmatrix.sync.aligned.m8n8.x4.shared.b16 {%0,%1,%2,%3}, [%4];"
                 : "=r"(r[0]), "=r"(r[1]), "=r"(r[2]), "=r"(r[3])
                 : "r"(saddr));
}

__device__ __forceinline__ void mma_tf32(float c[4],
                                         const uint32_t a[4],
                                         uint32_t b0, uint32_t b1) {
    asm volatile(
        "mma.sync.aligned.m16n8k8.row.col.f32.tf32.tf32.f32 "
        "{%0,%1,%2,%3}, {%4,%5,%6,%7}, {%8,%9}, {%0,%1,%2,%3};"
        : "+f"(c[0]), "+f"(c[1]), "+f"(c[2]), "+f"(c[3])
        : "r"(a[0]), "r"(a[1]), "r"(a[2]), "r"(a[3]), "r"(b0), "r"(b1));
}

// smem layout: tile [rows][16 k-floats] as 16B chunks, XOR swizzled.
__device__ __forceinline__ int sw16(int row, int c) {
    return row * 4 + (c ^ ((row >> 1) & 3));
}

// ---------------------------------------------------------------------------
// BIG tf32 GEMM: block 256x128, BK=16, 256 threads (8 warps, 4x2),
// warp tile 64x64. Double-buffered smem, 1 CTA/SM.
//   TRANS_B=false : B is [K,N] row-major   (C = A @ B)
//   TRANS_B=true  : B is [N,K] row-major   (C = A @ B^T)
// Requires M%256==0, N%128==0, K%16==0.
// ---------------------------------------------------------------------------
template <bool TRANS_B>
__global__ void __launch_bounds__(256, 1)
gemm_tf32_big(const float* __restrict__ A, const float* __restrict__ B,
              float* __restrict__ C, int M, int N, int K, float alpha)
{
    __shared__ float As[2][256 * 16];   // 32 KB
    __shared__ float Bs[2][128 * 16];   // 16 KB

    const int tid  = threadIdx.x;
    const int lane = tid & 31;
    const int wid  = tid >> 5;
    const int bm = blockIdx.y * 256;
    const int bn = blockIdx.x * 128;

    const int warp_m = wid & 3;         // 4 warps along M
    const int warp_n = wid >> 2;        // 2 warps along N
    const int m_base = warp_m * 64;
    const int n_base = warp_n * 64;

    // per-lane ldmatrix address components (identical math to validated kernel)
    const int a_row  = lane & 15;
    const int a_csel = (lane >> 4) & 1;
    const int b_row  = (lane & 7) + ((lane & 16) >> 1);
    const int b_csel = (lane >> 3) & 1;

    const uint32_t as_base0 = (uint32_t)__cvta_generic_to_shared(&As[0][0]);
    const uint32_t bs_base0 = (uint32_t)__cvta_generic_to_shared(&Bs[0][0]);
    const uint32_t a_buf_bytes = 256 * 16 * 4;
    const uint32_t b_buf_bytes = 128 * 16 * 4;

    // A loader: 256 rows x 4 chunks = 1024 float4, 4 per thread
    int ar[4];
#pragma unroll
    for (int i = 0; i < 4; ++i) ar[i] = (tid + 256 * i) >> 2;
    const int ac = tid & 3;
    // B loader coords (128 rows)
    const int b_r0 = tid >> 2;
    const int b_r1 = (tid + 256) >> 2;
    const int b_c  = tid & 3;
    const int bn_k0 = tid >> 7;        // 0..1
    const int bn_n0 = tid & 127;
    const int bn_k1 = (tid >> 7) + 2;  // 2..3

    float acc[4][8][4];
#pragma unroll
    for (int mt = 0; mt < 4; ++mt)
#pragma unroll
        for (int nt = 0; nt < 8; ++nt)
#pragma unroll
            for (int i = 0; i < 4; ++i) acc[mt][nt][i] = 0.0f;

    // prefetch registers
    float4 pa[4];
    float4 pb0, pb1;                 // TRANS_B path
    float  pc0[4], pc1[4];           // non-trans path

    auto ldg_tile = [&](int k0) {
#pragma unroll
        for (int i = 0; i < 4; ++i)
            pa[i] = *reinterpret_cast<const float4*>(
                &A[(size_t)(bm + ar[i]) * K + k0 + ac * 4]);
        if (TRANS_B) {
            pb0 = *reinterpret_cast<const float4*>(&B[(size_t)(bn + b_r0) * K + k0 + b_c * 4]);
            pb1 = *reinterpret_cast<const float4*>(&B[(size_t)(bn + b_r1) * K + k0 + b_c * 4]);
        } else {
#pragma unroll
            for (int j = 0; j < 4; ++j)
                pc0[j] = B[(size_t)(k0 + bn_k0 * 4 + j) * N + bn + bn_n0];
#pragma unroll
            for (int j = 0; j < 4; ++j)
                pc1[j] = B[(size_t)(k0 + bn_k1 * 4 + j) * N + bn + bn_n0];
        }
    };

    auto sts_tile = [&](int b) {
        float4 t;
#pragma unroll
        for (int i = 0; i < 4; ++i) {
            t.x = __uint_as_float(f2tf32(pa[i].x));
            t.y = __uint_as_float(f2tf32(pa[i].y));
            t.z = __uint_as_float(f2tf32(pa[i].z));
            t.w = __uint_as_float(f2tf32(pa[i].w));
            *reinterpret_cast<float4*>(&As[b][sw16(ar[i], ac) * 4]) = t;
        }
        if (TRANS_B) {
            t.x = __uint_as_float(f2tf32(pb0.x)); t.y = __uint_as_float(f2tf32(pb0.y));
            t.z = __uint_as_float(f2tf32(pb0.z)); t.w = __uint_as_float(f2tf32(pb0.w));
            *reinterpret_cast<float4*>(&Bs[b][sw16(b_r0, b_c) * 4]) = t;
            t.x = __uint_as_float(f2tf32(pb1.x)); t.y = __uint_as_float(f2tf32(pb1.y));
            t.z = __uint_as_float(f2tf32(pb1.z)); t.w = __uint_as_float(f2tf32(pb1.w));
            *reinterpret_cast<float4*>(&Bs[b][sw16(b_r1, b_c) * 4]) = t;
        } else {
            t.x = __uint_as_float(f2tf32(pc0[0])); t.y = __uint_as_float(f2tf32(pc0[1]));
            t.z = __uint_as_float(f2tf32(pc0[2])); t.w = __uint_as_float(f2tf32(pc0[3]));
            *reinterpret_cast<float4*>(&Bs[b][sw16(bn_n0, bn_k0) * 4]) = t;
            t.x = __uint_as_float(f2tf32(pc1[0])); t.y = __uint_as_float(f2tf32(pc1[1]));
            t.z = __uint_as_float(f2tf32(pc1[2])); t.w = __uint_as_float(f2tf32(pc1[3]));
            *reinterpret_cast<float4*>(&Bs[b][sw16(bn_n0, bn_k1) * 4]) = t;
        }
    };

    auto compute_tile = [&](int b) {
        const uint32_t as_b = as_base0 + (uint32_t)b * a_buf_bytes;
        const uint32_t bs_b = bs_base0 + (uint32_t)b * b_buf_bytes;
#pragma unroll
        for (int kk = 0; kk < 2; ++kk) {
            uint32_t af[4][4];
#pragma unroll
            for (int mt = 0; mt < 4; ++mt) {
                int m = m_base + mt * 16 + a_row;
                int c = 2 * kk + a_csel;
                ldsm4(af[mt], as_b + sw16(m, c) * 16);
            }
            uint32_t bf[4][4];
#pragma unroll
            for (int np = 0; np < 4; ++np) {
                int n = n_base + np * 16 + b_row;
                int c = 2 * kk + b_csel;
                ldsm4(bf[np], bs_b + sw16(n, c) * 16);
            }
#pragma unroll
            for (int mt = 0; mt < 4; ++mt)
#pragma unroll
                for (int nt = 0; nt < 8; ++nt)
                    mma_tf32(acc[mt][nt], af[mt],
                             bf[nt >> 1][(nt & 1) * 2],
                             bf[nt >> 1][(nt & 1) * 2 + 1]);
        }
    };

    // --- double-buffered main loop ---
    ldg_tile(0);
    sts_tile(0);
    __syncthreads();

    const int niter = K / 16;
    int buf = 0;
    for (int it = 1; it < niter; ++it) {
        ldg_tile(it * 16);
        compute_tile(buf);
        sts_tile(buf ^ 1);
        __syncthreads();
        buf ^= 1;
    }
    compute_tile(buf);

    // --- writeback ---
    const int g = lane >> 2;
    const int tq = lane & 3;
#pragma unroll
    for (int mt = 0; mt < 4; ++mt) {
#pragma unroll
        for (int nt = 0; nt < 8; ++nt) {
            const int col = bn + n_base + nt * 8 + tq * 2;
            const int r0 = bm + m_base + mt * 16 + g;
            const int r1 = r0 + 8;
            float2 v0, v1;
            v0.x = alpha * acc[mt][nt][0];
            v0.y = alpha * acc[mt][nt][1];
            v1.x = alpha * acc[mt][nt][2];
            v1.y = alpha * acc[mt][nt][3];
            *reinterpret_cast<float2*>(&C[(size_t)r0 * N + col]) = v0;
            *reinterpret_cast<float2*>(&C[(size_t)r1 * N + col]) = v1;
        }
    }
}

// ---------------------------------------------------------------------------
// 128x128 tf32 GEMM (validated R3 kernel) — used for the QKV projections.
// B is [K,N] row-major (C = A @ B). 256 threads, warp tile 64x32, 2 CTAs/SM.
// ---------------------------------------------------------------------------
__global__ void __launch_bounds__(256, 2)
gemm_tf32_proj(const float* __restrict__ A, const float* __restrict__ B,
               float* __restrict__ C, int M, int N, int K, float alpha)
{
    __shared__ float As[2][128 * 16];
    __shared__ float Bs[2][128 * 16];

    const int tid  = threadIdx.x;
    const int lane = tid & 31;
    const int wid  = tid >> 5;
    const int bm = blockIdx.y * 128;
    const int bn = blockIdx.x * 128;

    const int warp_m = wid & 1;
    const int warp_n = wid >> 1;
    const int m_base = warp_m * 64;
    const int n_base = warp_n * 32;

    const int a_row  = lane & 15;
    const int a_csel = (lane >> 4) & 1;
    const int b_row  = (lane & 7) + ((lane & 16) >> 1);
    const int b_csel = (lane >> 3) & 1;

    const uint32_t as_base0 = (uint32_t)__cvta_generic_to_shared(&As[0][0]);
    const uint32_t bs_base0 = (uint32_t)__cvta_generic_to_shared(&Bs[0][0]);
    const uint32_t buf_stride = 128 * 16 * 4;

    const int a_r0 = tid >> 2;
    const int a_c0 = tid & 3;
    const int a_r1 = (tid + 256) >> 2;
    const int bn_k0 = tid >> 7;
    const int bn_n0 = tid & 127;
    const int bn_k1 = (tid >> 7) + 2;

    float acc[4][4][4];
#pragma unroll
    for (int mt = 0; mt < 4; ++mt)
#pragma unroll
        for (int nt = 0; nt < 4; ++nt)
#pragma unroll
            for (int i = 0; i < 4; ++i) acc[mt][nt][i] = 0.0f;

    float4 pa0, pa1;
    float  pc0[4], pc1[4];

    auto ldg_tile = [&](int k0) {
        pa0 = *reinterpret_cast<const float4*>(&A[(size_t)(bm + a_r0) * K + k0 + a_c0 * 4]);
        pa1 = *reinterpret_cast<const float4*>(&A[(size_t)(bm + a_r1) * K + k0 + a_c0 * 4]);
#pragma unroll
        for (int j = 0; j < 4; ++j)
            pc0[j] = B[(size_t)(k0 + bn_k0 * 4 + j) * N + bn + bn_n0];
#pragma unroll
        for (int j = 0; j < 4; ++j)
            pc1[j] = B[(size_t)(k0 + bn_k1 * 4 + j) * N + bn + bn_n0];
    };

    auto sts_tile = [&](int b) {
        float4 t;
        t.x = __uint_as_float(f2tf32(pa0.x)); t.y = __uint_as_float(f2tf32(pa0.y));
        t.z = __uint_as_float(f2tf32(pa0.z)); t.w = __uint_as_float(f2tf32(pa0.w));
        *reinterpret_cast<float4*>(&As[b][sw16(a_r0, a_c0) * 4]) = t;
        t.x = __uint_as_float(f2tf32(pa1.x)); t.y = __uint_as_float(f2tf32(pa1.y));
        t.z = __uint_as_float(f2tf32(pa1.z)); t.w = __uint_as_float(f2tf32(pa1.w));
        *reinterpret_cast<float4*>(&As[b][sw16(a_r1, a_c0) * 4]) = t;
        t.x = __uint_as_float(f2tf32(pc0[0])); t.y = __uint_as_float(f2tf32(pc0[1]));
        t.z = __uint_as_float(f2tf32(pc0[2])); t.w = __uint_as_float(f2tf32(pc0[3]));
        *reinterpret_cast<float4*>(&Bs[b][sw16(bn_n0, bn_k0) * 4]) = t;
        t.x = __uint_as_float(f2tf32(pc1[0])); t.y = __uint_as_float(f2tf32(pc1[1]));
        t.z = __uint_as_float(f2tf32(pc1[2])); t.w = __uint_as_float(f2tf32(pc1[3]));
        *reinterpret_cast<float4*>(&Bs[b][sw16(bn_n0, bn_k1) * 4]) = t;
    };

    auto compute_tile = [&](int b) {
        const uint32_t as_b = as_base0 + (uint32_t)b * buf_stride;
        const uint32_t bs_b = bs_base0 + (uint32_t)b * buf_stride;
#pragma unroll
        for (int kk = 0; kk < 2; ++kk) {
            uint32_t af[4][4];
#pragma unroll
            for (int mt = 0; mt < 4; ++mt) {
                int m = m_base + mt * 16 + a_row;
                int c = 2 * kk + a_csel;
                ldsm4(af[mt], as_b + sw16(m, c) * 16);
            }
            uint32_t bf[2][4];
#pragma unroll
            for (int np = 0; np < 2; ++np) {
                int n = n_base + np * 16 + b_row;
                int c = 2 * kk + b_csel;
                ldsm4(bf[np], bs_b + sw16(n, c) * 16);
            }
#pragma unroll
            for (int mt = 0; mt < 4; ++mt)
#pragma unroll
                for (int nt = 0; nt < 4; ++nt)
                    mma_tf32(acc[mt][nt], af[mt],
                             bf[nt >> 1][(nt & 1) * 2],
                             bf[nt >> 1][(nt & 1) * 2 + 1]);
        }
    };

    ldg_tile(0);
    sts_tile(0);
    __syncthreads();

    const int niter = K / 16;
    int buf = 0;
    for (int it = 1; it < niter; ++it) {
        ldg_tile(it * 16);
        compute_tile(buf);
        sts_tile(buf ^ 1);
        __syncthreads();
        buf ^= 1;
    }
    compute_tile(buf);

    const int g = lane >> 2;
    const int tq = lane & 3;
#pragma unroll
    for (int mt = 0; mt < 4; ++mt) {
#pragma unroll
        for (int nt = 0; nt < 4; ++nt) {
            const int col = bn + n_base + nt * 8 + tq * 2;
            const int r0 = bm + m_base + mt * 16 + g;
            const int r1 = r0 + 8;
            float2 v0, v1;
            v0.x = alpha * acc[mt][nt][0];
            v0.y = alpha * acc[mt][nt][1];
            v1.x = alpha * acc[mt][nt][2];
            v1.y = alpha * acc[mt][nt][3];
            *reinterpret_cast<float2*>(&C[(size_t)r0 * N + col]) = v0;
            *reinterpret_cast<float2*>(&C[(size_t)r1 * N + col]) = v1;
        }
    }
}

// ---------------------------------------------------------------------------
// Row softmax over S [SEQ, SEQ]. One block per row; row resident in registers.
// ---------------------------------------------------------------------------
__global__ void __launch_bounds__(256)
softmax_kernel(float* __restrict__ S)
{
    const int row = blockIdx.x;
    const int tid = threadIdx.x;
    float* p = S + (size_t)row * SEQ;

    __shared__ float sm_red[8];
    __shared__ float sm_bcast;

    float v[16];
#pragma unroll
    for (int it = 0; it < 4; ++it) {
        float4 t = *reinterpret_cast<const float4*>(&p[it * 1024 + tid * 4]);
        v[it * 4 + 0] = t.x; v[it * 4 + 1] = t.y;
        v[it * 4 + 2] = t.z; v[it * 4 + 3] = t.w;
    }

    float m = v[0];
#pragma unroll
    for (int i = 1; i < 16; ++i) m = fmaxf(m, v[i]);
#pragma unroll
    for (int o = 16; o > 0; o >>= 1) m = fmaxf(m, __shfl_xor_sync(0xffffffffu, m, o));
    if ((tid & 31) == 0) sm_red[tid >> 5] = m;
    __syncthreads();
    if (tid == 0) {
        float mm = sm_red[0];
#pragma unroll
        for (int w = 1; w < 8; ++w) mm = fmaxf(mm, sm_red[w]);
        sm_bcast = mm;
    }
    __syncthreads();
    m = sm_bcast;
    __syncthreads();

    float s = 0.0f;
#pragma unroll
    for (int i = 0; i < 16; ++i) {
        v[i] = __expf(v[i] - m);
        s += v[i];
    }
#pragma unroll
    for (int o = 16; o > 0; o >>= 1) s += __shfl_xor_sync(0xffffffffu, s, o);
    if ((tid & 31) == 0) sm_red[tid >> 5] = s;
    __syncthreads();
    if (tid == 0) {
        float ss = sm_red[0];
#pragma unroll
        for (int w = 1; w < 8; ++w) ss += sm_red[w];
        sm_bcast = ss;
    }
    __syncthreads();
    const float inv = 1.0f / sm_bcast;

#pragma unroll
    for (int it = 0; it < 4; ++it) {
        float4 t;
        t.x = v[it * 4 + 0] * inv; t.y = v[it * 4 + 1] * inv;
        t.z = v[it * 4 + 2] * inv; t.w = v[it * 4 + 3] * inv;
        *reinterpret_cast<float4*>(&p[it * 1024 + tid * 4]) = t;
    }
}

// ---------------------------------------------------------------------------
extern "C" void kernel_launch(void* const* d_in, const int* in_sizes, int n_in,
                              void* d_out, int out_size)
{
    const float* x  = (const float*)d_in[0];
    const float* Wq = (const float*)d_in[1];
    const float* Wk = (const float*)d_in[2];
    const float* Wv = (const float*)d_in[3];
    float* out = (float*)d_out;

    float* Q;  cudaGetSymbolAddress((void**)&Q,  g_Q);
    float* K_; cudaGetSymbolAddress((void**)&K_, g_K);
    float* V;  cudaGetSymbolAddress((void**)&V,  g_V);
    float* S;  cudaGetSymbolAddress((void**)&S,  g_S);

    const float inv_sqrt_d = 0.036084391824351615f;  // 1/sqrt(768)

    dim3 blk(256);
    dim3 grid_proj(DOUT / 128, SEQ / 128);   // (6, 32)
    dim3 grid_qk(SEQ / 128, SEQ / 256);      // (32, 16)
    dim3 grid_av(DOUT / 128, SEQ / 256);     // (6, 16)

    // Q, K, V projections (128x128 kernel, 2 CTAs/SM)
    gemm_tf32_proj<<<grid_proj, blk>>>(x, Wq, Q,  SEQ, DOUT, DIN, 1.0f);
    gemm_tf32_proj<<<grid_proj, blk>>>(x, Wk, K_, SEQ, DOUT, DIN, 1.0f);
    gemm_tf32_proj<<<grid_proj, blk>>>(x, Wv, V,  SEQ, DOUT, DIN, 1.0f);

    // scores = (Q @ K^T) / sqrt(d)  (256x128 kernel)
    gemm_tf32_big<true><<<grid_qk, blk>>>(Q, K_, S, SEQ, SEQ, DOUT, inv_sqrt_d);

    // row softmax
    softmax_kernel<<<SEQ, blk>>>(S);

    // out = weights @ V  (256x128 kernel)
    gemm_tf32_big<false><<<grid_av, blk>>>(S, V, out, SEQ, DOUT, SEQ, 1.0f);
}

// round 5
// speedup vs baseline: 1.1309x; 1.1309x over previous
#include <cuda_runtime.h>
#include <cstdint>

#define SEQ  4096
#define DIN  768
#define DOUT 768

// Scratch (allocation-free: __device__ globals).
__device__ float g_Q[SEQ * DOUT];
__device__ float g_K[SEQ * DOUT];
__device__ float g_V[SEQ * DOUT];
__device__ float g_S[(size_t)SEQ * SEQ];

// ---------------------------------------------------------------------------
// helpers
// ---------------------------------------------------------------------------
__device__ __forceinline__ uint32_t f2tf32(float f) {
    uint32_t r;
    asm("cvt.rna.tf32.f32 %0, %1;" : "=r"(r) : "f"(f));
    return r;
}

__device__ __forceinline__ void ldsm4(uint32_t r[4], uint32_t saddr) {
    asm volatile("ldmatrix.sync.aligned.m8n8.x4.shared.b16 {%0,%1,%2,%3}, [%4];"
                 : "=r"(r[0]), "=r"(r[1]), "=r"(r[2]), "=r"(r[3])
                 : "r"(saddr));
}

__device__ __forceinline__ void mma_tf32(float c[4],
                                         const uint32_t a[4],
                                         uint32_t b0, uint32_t b1) {
    asm volatile(
        "mma.sync.aligned.m16n8k8.row.col.f32.tf32.tf32.f32 "
        "{%0,%1,%2,%3}, {%4,%5,%6,%7}, {%8,%9}, {%0,%1,%2,%3};"
        : "+f"(c[0]), "+f"(c[1]), "+f"(c[2]), "+f"(c[3])
        : "r"(a[0]), "r"(a[1]), "r"(a[2]), "r"(a[3]), "r"(b0), "r"(b1));
}

// smem layout: tile [rows][16 k-floats] as 16B chunks, XOR swizzled.
__device__ __forceinline__ int sw16(int row, int c) {
    return row * 4 + (c ^ ((row >> 1) & 3));
}

// ---------------------------------------------------------------------------
// Wide-warp tf32 GEMM: block 128x128, BK=16, 128 threads (4 warps, 2x2),
// warp tile 64x64. Double-buffered smem, 2 CTAs/SM.
//   TRANS_B=false : B is [K,N] row-major   (C = A @ B)
//   TRANS_B=true  : B is [N,K] row-major   (C = A @ B^T)
// Requires M%128==0, N%128==0, K%16==0.
// ---------------------------------------------------------------------------
template <bool TRANS_B>
__global__ void __launch_bounds__(128, 2)
gemm_tf32_ww(const float* __restrict__ A, const float* __restrict__ B,
             float* __restrict__ C, int M, int N, int K, float alpha)
{
    __shared__ float As[2][128 * 16];   // 16 KB
    __shared__ float Bs[2][128 * 16];   // 16 KB

    const int tid  = threadIdx.x;       // 0..127
    const int lane = tid & 31;
    const int wid  = tid >> 5;          // 0..3
    const int bm = blockIdx.y * 128;
    const int bn = blockIdx.x * 128;

    const int warp_m = wid & 1;         // 2 warps along M
    const int warp_n = wid >> 1;        // 2 warps along N
    const int m_base = warp_m * 64;
    const int n_base = warp_n * 64;

    // per-lane ldmatrix address components (validated mapping)
    const int a_row  = lane & 15;
    const int a_csel = (lane >> 4) & 1;
    const int b_row  = (lane & 7) + ((lane & 16) >> 1);
    const int b_csel = (lane >> 3) & 1;

    const uint32_t as_base0 = (uint32_t)__cvta_generic_to_shared(&As[0][0]);
    const uint32_t bs_base0 = (uint32_t)__cvta_generic_to_shared(&Bs[0][0]);
    const uint32_t buf_bytes = 128 * 16 * 4;

    // Loader: tile = 128 rows x 4 chunks = 512 float4; 128 threads -> 4 each.
    // idx = tid + 128*i : row = idx>>2, chunk = idx&3 (== tid&3).
    int lr[4];
#pragma unroll
    for (int i = 0; i < 4; ++i) lr[i] = (tid + 128 * i) >> 2;
    const int lc = tid & 3;
    // B non-trans gather: idx = tid + 128*i -> kc = i, n = tid.
    // thread gathers pc[i][j] = B[(k0 + i*4 + j)*N + bn + tid]

    float acc[4][8][4];
#pragma unroll
    for (int mt = 0; mt < 4; ++mt)
#pragma unroll
        for (int nt = 0; nt < 8; ++nt)
#pragma unroll
            for (int i = 0; i < 4; ++i) acc[mt][nt][i] = 0.0f;

    // prefetch registers
    float4 pa[4];
    float4 pb[4];                    // TRANS_B path
    float  pc[4][4];                 // non-trans path (gathered columns)

    auto ldg_tile = [&](int k0) {
#pragma unroll
        for (int i = 0; i < 4; ++i)
            pa[i] = *reinterpret_cast<const float4*>(
                &A[(size_t)(bm + lr[i]) * K + k0 + lc * 4]);
        if (TRANS_B) {
#pragma unroll
            for (int i = 0; i < 4; ++i)
                pb[i] = *reinterpret_cast<const float4*>(
                    &B[(size_t)(bn + lr[i]) * K + k0 + lc * 4]);
        } else {
#pragma unroll
            for (int i = 0; i < 4; ++i)
#pragma unroll
                for (int j = 0; j < 4; ++j)
                    pc[i][j] = B[(size_t)(k0 + i * 4 + j) * N + bn + tid];
        }
    };

    auto sts_tile = [&](int b) {
        float4 t;
#pragma unroll
        for (int i = 0; i < 4; ++i) {
            t.x = __uint_as_float(f2tf32(pa[i].x));
            t.y = __uint_as_float(f2tf32(pa[i].y));
            t.z = __uint_as_float(f2tf32(pa[i].z));
            t.w = __uint_as_float(f2tf32(pa[i].w));
            *reinterpret_cast<float4*>(&As[b][sw16(lr[i], lc) * 4]) = t;
        }
        if (TRANS_B) {
#pragma unroll
            for (int i = 0; i < 4; ++i) {
                t.x = __uint_as_float(f2tf32(pb[i].x));
                t.y = __uint_as_float(f2tf32(pb[i].y));
                t.z = __uint_as_float(f2tf32(pb[i].z));
                t.w = __uint_as_float(f2tf32(pb[i].w));
                *reinterpret_cast<float4*>(&Bs[b][sw16(lr[i], lc) * 4]) = t;
            }
        } else {
#pragma unroll
            for (int i = 0; i < 4; ++i) {
                t.x = __uint_as_float(f2tf32(pc[i][0]));
                t.y = __uint_as_float(f2tf32(pc[i][1]));
                t.z = __uint_as_float(f2tf32(pc[i][2]));
                t.w = __uint_as_float(f2tf32(pc[i][3]));
                // row = n = tid, chunk = kc = i
                *reinterpret_cast<float4*>(&Bs[b][sw16(tid, i) * 4]) = t;
            }
        }
    };

    auto compute_tile = [&](int b) {
        const uint32_t as_b = as_base0 + (uint32_t)b * buf_bytes;
        const uint32_t bs_b = bs_base0 + (uint32_t)b * buf_bytes;
#pragma unroll
        for (int kk = 0; kk < 2; ++kk) {
            uint32_t af[4][4];
#pragma unroll
            for (int mt = 0; mt < 4; ++mt) {
                int m = m_base + mt * 16 + a_row;
                int c = 2 * kk + a_csel;
                ldsm4(af[mt], as_b + sw16(m, c) * 16);
            }
            uint32_t bf[4][4];
#pragma unroll
            for (int np = 0; np < 4; ++np) {
                int n = n_base + np * 16 + b_row;
                int c = 2 * kk + b_csel;
                ldsm4(bf[np], bs_b + sw16(n, c) * 16);
            }
#pragma unroll
            for (int mt = 0; mt < 4; ++mt)
#pragma unroll
                for (int nt = 0; nt < 8; ++nt)
                    mma_tf32(acc[mt][nt], af[mt],
                             bf[nt >> 1][(nt & 1) * 2],
                             bf[nt >> 1][(nt & 1) * 2 + 1]);
        }
    };

    // --- double-buffered main loop ---
    ldg_tile(0);
    sts_tile(0);
    __syncthreads();

    const int niter = K / 16;
    int buf = 0;
    for (int it = 1; it < niter; ++it) {
        ldg_tile(it * 16);
        compute_tile(buf);
        sts_tile(buf ^ 1);
        __syncthreads();
        buf ^= 1;
    }
    compute_tile(buf);

    // --- writeback ---
    const int g = lane >> 2;
    const int tq = lane & 3;
#pragma unroll
    for (int mt = 0; mt < 4; ++mt) {
#pragma unroll
        for (int nt = 0; nt < 8; ++nt) {
            const int col = bn + n_base + nt * 8 + tq * 2;
            const int r0 = bm + m_base + mt * 16 + g;
            const int r1 = r0 + 8;
            float2 v0, v1;
            v0.x = alpha * acc[mt][nt][0];
            v0.y = alpha * acc[mt][nt][1];
            v1.x = alpha * acc[mt][nt][2];
            v1.y = alpha * acc[mt][nt][3];
            *reinterpret_cast<float2*>(&C[(size_t)r0 * N + col]) = v0;
            *reinterpret_cast<float2*>(&C[(size_t)r1 * N + col]) = v1;
        }
    }
}

// ---------------------------------------------------------------------------
// 128x128 tf32 GEMM (validated R3 kernel) — used for the QKV projections.
// B is [K,N] row-major (C = A @ B). 256 threads, warp tile 64x32, 2 CTAs/SM.
// ---------------------------------------------------------------------------
__global__ void __launch_bounds__(256, 2)
gemm_tf32_proj(const float* __restrict__ A, const float* __restrict__ B,
               float* __restrict__ C, int M, int N, int K, float alpha)
{
    __shared__ float As[2][128 * 16];
    __shared__ float Bs[2][128 * 16];

    const int tid  = threadIdx.x;
    const int lane = tid & 31;
    const int wid  = tid >> 5;
    const int bm = blockIdx.y * 128;
    const int bn = blockIdx.x * 128;

    const int warp_m = wid & 1;
    const int warp_n = wid >> 1;
    const int m_base = warp_m * 64;
    const int n_base = warp_n * 32;

    const int a_row  = lane & 15;
    const int a_csel = (lane >> 4) & 1;
    const int b_row  = (lane & 7) + ((lane & 16) >> 1);
    const int b_csel = (lane >> 3) & 1;

    const uint32_t as_base0 = (uint32_t)__cvta_generic_to_shared(&As[0][0]);
    const uint32_t bs_base0 = (uint32_t)__cvta_generic_to_shared(&Bs[0][0]);
    const uint32_t buf_stride = 128 * 16 * 4;

    const int a_r0 = tid >> 2;
    const int a_c0 = tid & 3;
    const int a_r1 = (tid + 256) >> 2;
    const int bn_k0 = tid >> 7;
    const int bn_n0 = tid & 127;
    const int bn_k1 = (tid >> 7) + 2;

    float acc[4][4][4];
#pragma unroll
    for (int mt = 0; mt < 4; ++mt)
#pragma unroll
        for (int nt = 0; nt < 4; ++nt)
#pragma unroll
            for (int i = 0; i < 4; ++i) acc[mt][nt][i] = 0.0f;

    float4 pa0, pa1;
    float  pc0[4], pc1[4];

    auto ldg_tile = [&](int k0) {
        pa0 = *reinterpret_cast<const float4*>(&A[(size_t)(bm + a_r0) * K + k0 + a_c0 * 4]);
        pa1 = *reinterpret_cast<const float4*>(&A[(size_t)(bm + a_r1) * K + k0 + a_c0 * 4]);
#pragma unroll
        for (int j = 0; j < 4; ++j)
            pc0[j] = B[(size_t)(k0 + bn_k0 * 4 + j) * N + bn + bn_n0];
#pragma unroll
        for (int j = 0; j < 4; ++j)
            pc1[j] = B[(size_t)(k0 + bn_k1 * 4 + j) * N + bn + bn_n0];
    };

    auto sts_tile = [&](int b) {
        float4 t;
        t.x = __uint_as_float(f2tf32(pa0.x)); t.y = __uint_as_float(f2tf32(pa0.y));
        t.z = __uint_as_float(f2tf32(pa0.z)); t.w = __uint_as_float(f2tf32(pa0.w));
        *reinterpret_cast<float4*>(&As[b][sw16(a_r0, a_c0) * 4]) = t;
        t.x = __uint_as_float(f2tf32(pa1.x)); t.y = __uint_as_float(f2tf32(pa1.y));
        t.z = __uint_as_float(f2tf32(pa1.z)); t.w = __uint_as_float(f2tf32(pa1.w));
        *reinterpret_cast<float4*>(&As[b][sw16(a_r1, a_c0) * 4]) = t;
        t.x = __uint_as_float(f2tf32(pc0[0])); t.y = __uint_as_float(f2tf32(pc0[1]));
        t.z = __uint_as_float(f2tf32(pc0[2])); t.w = __uint_as_float(f2tf32(pc0[3]));
        *reinterpret_cast<float4*>(&Bs[b][sw16(bn_n0, bn_k0) * 4]) = t;
        t.x = __uint_as_float(f2tf32(pc1[0])); t.y = __uint_as_float(f2tf32(pc1[1]));
        t.z = __uint_as_float(f2tf32(pc1[2])); t.w = __uint_as_float(f2tf32(pc1[3]));
        *reinterpret_cast<float4*>(&Bs[b][sw16(bn_n0, bn_k1) * 4]) = t;
    };

    auto compute_tile = [&](int b) {
        const uint32_t as_b = as_base0 + (uint32_t)b * buf_stride;
        const uint32_t bs_b = bs_base0 + (uint32_t)b * buf_stride;
#pragma unroll
        for (int kk = 0; kk < 2; ++kk) {
            uint32_t af[4][4];
#pragma unroll
            for (int mt = 0; mt < 4; ++mt) {
                int m = m_base + mt * 16 + a_row;
                int c = 2 * kk + a_csel;
                ldsm4(af[mt], as_b + sw16(m, c) * 16);
            }
            uint32_t bf[2][4];
#pragma unroll
            for (int np = 0; np < 2; ++np) {
                int n = n_base + np * 16 + b_row;
                int c = 2 * kk + b_csel;
                ldsm4(bf[np], bs_b + sw16(n, c) * 16);
            }
#pragma unroll
            for (int mt = 0; mt < 4; ++mt)
#pragma unroll
                for (int nt = 0; nt < 4; ++nt)
                    mma_tf32(acc[mt][nt], af[mt],
                             bf[nt >> 1][(nt & 1) * 2],
                             bf[nt >> 1][(nt & 1) * 2 + 1]);
        }
    };

    ldg_tile(0);
    sts_tile(0);
    __syncthreads();

    const int niter = K / 16;
    int buf = 0;
    for (int it = 1; it < niter; ++it) {
        ldg_tile(it * 16);
        compute_tile(buf);
        sts_tile(buf ^ 1);
        __syncthreads();
        buf ^= 1;
    }
    compute_tile(buf);

    const int g = lane >> 2;
    const int tq = lane & 3;
#pragma unroll
    for (int mt = 0; mt < 4; ++mt) {
#pragma unroll
        for (int nt = 0; nt < 4; ++nt) {
            const int col = bn + n_base + nt * 8 + tq * 2;
            const int r0 = bm + m_base + mt * 16 + g;
            const int r1 = r0 + 8;
            float2 v0, v1;
            v0.x = alpha * acc[mt][nt][0];
            v0.y = alpha * acc[mt][nt][1];
            v1.x = alpha * acc[mt][nt][2];
            v1.y = alpha * acc[mt][nt][3];
            *reinterpret_cast<float2*>(&C[(size_t)r0 * N + col]) = v0;
            *reinterpret_cast<float2*>(&C[(size_t)r1 * N + col]) = v1;
        }
    }
}

// ---------------------------------------------------------------------------
// Row softmax over S [SEQ, SEQ]. One block per row; row resident in registers.
// ---------------------------------------------------------------------------
__global__ void __launch_bounds__(256)
softmax_kernel(float* __restrict__ S)
{
    const int row = blockIdx.x;
    const int tid = threadIdx.x;
    float* p = S + (size_t)row * SEQ;

    __shared__ float sm_red[8];
    __shared__ float sm_bcast;

    float v[16];
#pragma unroll
    for (int it = 0; it < 4; ++it) {
        float4 t = *reinterpret_cast<const float4*>(&p[it * 1024 + tid * 4]);
        v[it * 4 + 0] = t.x; v[it * 4 + 1] = t.y;
        v[it * 4 + 2] = t.z; v[it * 4 + 3] = t.w;
    }

    float m = v[0];
#pragma unroll
    for (int i = 1; i < 16; ++i) m = fmaxf(m, v[i]);
#pragma unroll
    for (int o = 16; o > 0; o >>= 1) m = fmaxf(m, __shfl_xor_sync(0xffffffffu, m, o));
    if ((tid & 31) == 0) sm_red[tid >> 5] = m;
    __syncthreads();
    if (tid == 0) {
        float mm = sm_red[0];
#pragma unroll
        for (int w = 1; w < 8; ++w) mm = fmaxf(mm, sm_red[w]);
        sm_bcast = mm;
    }
    __syncthreads();
    m = sm_bcast;
    __syncthreads();

    float s = 0.0f;
#pragma unroll
    for (int i = 0; i < 16; ++i) {
        v[i] = __expf(v[i] - m);
        s += v[i];
    }
#pragma unroll
    for (int o = 16; o > 0; o >>= 1) s += __shfl_xor_sync(0xffffffffu, s, o);
    if ((tid & 31) == 0) sm_red[tid >> 5] = s;
    __syncthreads();
    if (tid == 0) {
        float ss = sm_red[0];
#pragma unroll
        for (int w = 1; w < 8; ++w) ss += sm_red[w];
        sm_bcast = ss;
    }
    __syncthreads();
    const float inv = 1.0f / sm_bcast;

#pragma unroll
    for (int it = 0; it < 4; ++it) {
        float4 t;
        t.x = v[it * 4 + 0] * inv; t.y = v[it * 4 + 1] * inv;
        t.z = v[it * 4 + 2] * inv; t.w = v[it * 4 + 3] * inv;
        *reinterpret_cast<float4*>(&p[it * 1024 + tid * 4]) = t;
    }
}

// ---------------------------------------------------------------------------
extern "C" void kernel_launch(void* const* d_in, const int* in_sizes, int n_in,
                              void* d_out, int out_size)
{
    const float* x  = (const float*)d_in[0];
    const float* Wq = (const float*)d_in[1];
    const float* Wk = (const float*)d_in[2];
    const float* Wv = (const float*)d_in[3];
    float* out = (float*)d_out;

    float* Q;  cudaGetSymbolAddress((void**)&Q,  g_Q);
    float* K_; cudaGetSymbolAddress((void**)&K_, g_K);
    float* V;  cudaGetSymbolAddress((void**)&V,  g_V);
    float* S;  cudaGetSymbolAddress((void**)&S,  g_S);

    const float inv_sqrt_d = 0.036084391824351615f;  // 1/sqrt(768)

    dim3 grid_proj(DOUT / 128, SEQ / 128);   // (6, 32)
    dim3 grid_ss(SEQ / 128, SEQ / 128);      // (32, 32)
    dim3 grid_av(DOUT / 128, SEQ / 128);     // (6, 32)

    // Q, K, V projections (validated 256-thread kernel, 2 CTAs/SM)
    gemm_tf32_proj<<<grid_proj, 256>>>(x, Wq, Q,  SEQ, DOUT, DIN, 1.0f);
    gemm_tf32_proj<<<grid_proj, 256>>>(x, Wk, K_, SEQ, DOUT, DIN, 1.0f);
    gemm_tf32_proj<<<grid_proj, 256>>>(x, Wv, V,  SEQ, DOUT, DIN, 1.0f);

    // scores = (Q @ K^T) / sqrt(d)  (wide-warp kernel, 128 threads)
    gemm_tf32_ww<true><<<grid_ss, 128>>>(Q, K_, S, SEQ, SEQ, DOUT, inv_sqrt_d);

    // row softmax
    softmax_kernel<<<SEQ, 256>>>(S);

    // out = weights @ V  (wide-warp kernel)
    gemm_tf32_ww<false><<<grid_av, 128>>>(S, V, out, SEQ, DOUT, SEQ, 1.0f);
}

// round 7
// speedup vs baseline: 1.2905x; 1.1411x over previous
#include <cuda_runtime.h>
#include <cstdint>

#define SEQ  4096
#define DIN  768
#define DOUT 768

// Scratch (allocation-free: __device__ globals).
__device__ float g_Q[SEQ * DOUT];
__device__ float g_K[SEQ * DOUT];
__device__ float g_V[SEQ * DOUT];
__device__ float g_E[(size_t)SEQ * SEQ];   // exp(scores)
__device__ float g_inv[SEQ];               // 1 / rowsum(E)

// ---------------------------------------------------------------------------
// helpers
// ---------------------------------------------------------------------------
__device__ __forceinline__ uint32_t f2tf32(float f) {
    uint32_t r;
    asm("cvt.rna.tf32.f32 %0, %1;" : "=r"(r) : "f"(f));
    return r;
}

__device__ __forceinline__ void ldsm4(uint32_t r[4], uint32_t saddr) {
    asm volatile("ldmatrix.sync.aligned.m8n8.x4.shared.b16 {%0,%1,%2,%3}, [%4];"
                 : "=r"(r[0]), "=r"(r[1]), "=r"(r[2]), "=r"(r[3])
                 : "r"(saddr));
}

__device__ __forceinline__ void mma_tf32(float c[4],
                                         const uint32_t a[4],
                                         uint32_t b0, uint32_t b1) {
    asm volatile(
        "mma.sync.aligned.m16n8k8.row.col.f32.tf32.tf32.f32 "
        "{%0,%1,%2,%3}, {%4,%5,%6,%7}, {%8,%9}, {%0,%1,%2,%3};"
        : "+f"(c[0]), "+f"(c[1]), "+f"(c[2]), "+f"(c[3])
        : "r"(a[0]), "r"(a[1]), "r"(a[2]), "r"(a[3]), "r"(b0), "r"(b1));
}

// smem layout: tile [rows][16 k-floats] as 16B chunks, XOR swizzled.
__device__ __forceinline__ int sw16(int row, int c) {
    return row * 4 + (c ^ ((row >> 1) & 3));
}

// ---------------------------------------------------------------------------
// Wide-warp tf32 GEMM core: block 128x128, BK=16, 128 threads (4 warps 2x2),
// warp tile 64x64, double-buffered smem, 2 CTAs/SM.
// MODE 0: C = alpha*acc,            B is [K,N]    (A @ B)
// MODE 1: C = exp(alpha*acc),       B is [N,K]    (A @ B^T), fused exp
// MODE 2: C = acc * invsum[row],    B is [K,N]    (A @ B), fused normalize
// ---------------------------------------------------------------------------
template <int MODE>
__global__ void __launch_bounds__(128, 2)
gemm_tf32_ww(const float* __restrict__ A, const float* __restrict__ B,
             float* __restrict__ C, int M, int N, int K, float alpha,
             const float* __restrict__ invsum)
{
    constexpr bool TRANS_B = (MODE == 1);

    __shared__ float As[2][128 * 16];   // 16 KB
    __shared__ float Bs[2][128 * 16];   // 16 KB

    const int tid  = threadIdx.x;       // 0..127
    const int lane = tid & 31;
    const int wid  = tid >> 5;          // 0..3
    const int bm = blockIdx.y * 128;
    const int bn = blockIdx.x * 128;

    const int warp_m = wid & 1;
    const int warp_n = wid >> 1;
    const int m_base = warp_m * 64;
    const int n_base = warp_n * 64;

    const int a_row  = lane & 15;
    const int a_csel = (lane >> 4) & 1;
    const int b_row  = (lane & 7) + ((lane & 16) >> 1);
    const int b_csel = (lane >> 3) & 1;

    const uint32_t as_base0 = (uint32_t)__cvta_generic_to_shared(&As[0][0]);
    const uint32_t bs_base0 = (uint32_t)__cvta_generic_to_shared(&Bs[0][0]);
    const uint32_t buf_bytes = 128 * 16 * 4;

    int lr[4];
#pragma unroll
    for (int i = 0; i < 4; ++i) lr[i] = (tid + 128 * i) >> 2;
    const int lc = tid & 3;

    float acc[4][8][4];
#pragma unroll
    for (int mt = 0; mt < 4; ++mt)
#pragma unroll
        for (int nt = 0; nt < 8; ++nt)
#pragma unroll
            for (int i = 0; i < 4; ++i) acc[mt][nt][i] = 0.0f;

    float4 pa[4];
    float4 pb[4];
    float  pc[4][4];

    auto ldg_tile = [&](int k0) {
#pragma unroll
        for (int i = 0; i < 4; ++i)
            pa[i] = *reinterpret_cast<const float4*>(
                &A[(size_t)(bm + lr[i]) * K + k0 + lc * 4]);
        if (TRANS_B) {
#pragma unroll
            for (int i = 0; i < 4; ++i)
                pb[i] = *reinterpret_cast<const float4*>(
                    &B[(size_t)(bn + lr[i]) * K + k0 + lc * 4]);
        } else {
#pragma unroll
            for (int i = 0; i < 4; ++i)
#pragma unroll
                for (int j = 0; j < 4; ++j)
                    pc[i][j] = B[(size_t)(k0 + i * 4 + j) * N + bn + tid];
        }
    };

    auto sts_tile = [&](int b) {
        float4 t;
#pragma unroll
        for (int i = 0; i < 4; ++i) {
            t.x = __uint_as_float(f2tf32(pa[i].x));
            t.y = __uint_as_float(f2tf32(pa[i].y));
            t.z = __uint_as_float(f2tf32(pa[i].z));
            t.w = __uint_as_float(f2tf32(pa[i].w));
            *reinterpret_cast<float4*>(&As[b][sw16(lr[i], lc) * 4]) = t;
        }
        if (TRANS_B) {
#pragma unroll
            for (int i = 0; i < 4; ++i) {
                t.x = __uint_as_float(f2tf32(pb[i].x));
                t.y = __uint_as_float(f2tf32(pb[i].y));
                t.z = __uint_as_float(f2tf32(pb[i].z));
                t.w = __uint_as_float(f2tf32(pb[i].w));
                *reinterpret_cast<float4*>(&Bs[b][sw16(lr[i], lc) * 4]) = t;
            }
        } else {
#pragma unroll
            for (int i = 0; i < 4; ++i) {
                t.x = __uint_as_float(f2tf32(pc[i][0]));
                t.y = __uint_as_float(f2tf32(pc[i][1]));
                t.z = __uint_as_float(f2tf32(pc[i][2]));
                t.w = __uint_as_float(f2tf32(pc[i][3]));
                *reinterpret_cast<float4*>(&Bs[b][sw16(tid, i) * 4]) = t;
            }
        }
    };

    auto compute_tile = [&](int b) {
        const uint32_t as_b = as_base0 + (uint32_t)b * buf_bytes;
        const uint32_t bs_b = bs_base0 + (uint32_t)b * buf_bytes;
#pragma unroll
        for (int kk = 0; kk < 2; ++kk) {
            uint32_t af[4][4];
#pragma unroll
            for (int mt = 0; mt < 4; ++mt) {
                int m = m_base + mt * 16 + a_row;
                int c = 2 * kk + a_csel;
                ldsm4(af[mt], as_b + sw16(m, c) * 16);
            }
            uint32_t bf[4][4];
#pragma unroll
            for (int np = 0; np < 4; ++np) {
                int n = n_base + np * 16 + b_row;
                int c = 2 * kk + b_csel;
                ldsm4(bf[np], bs_b + sw16(n, c) * 16);
            }
#pragma unroll
            for (int mt = 0; mt < 4; ++mt)
#pragma unroll
                for (int nt = 0; nt < 8; ++nt)
                    mma_tf32(acc[mt][nt], af[mt],
                             bf[nt >> 1][(nt & 1) * 2],
                             bf[nt >> 1][(nt & 1) * 2 + 1]);
        }
    };

    ldg_tile(0);
    sts_tile(0);
    __syncthreads();

    const int niter = K / 16;
    int buf = 0;
    for (int it = 1; it < niter; ++it) {
        ldg_tile(it * 16);
        compute_tile(buf);
        sts_tile(buf ^ 1);
        __syncthreads();
        buf ^= 1;
    }
    compute_tile(buf);

    // --- writeback with fused epilogue ---
    const int g = lane >> 2;
    const int tq = lane & 3;
#pragma unroll
    for (int mt = 0; mt < 4; ++mt) {
        const int r0 = bm + m_base + mt * 16 + g;
        const int r1 = r0 + 8;
        float s0 = 1.0f, s1 = 1.0f;
        if (MODE == 2) { s0 = invsum[r0]; s1 = invsum[r1]; }
#pragma unroll
        for (int nt = 0; nt < 8; ++nt) {
            const int col = bn + n_base + nt * 8 + tq * 2;
            float2 v0, v1;
            if (MODE == 0) {
                v0.x = alpha * acc[mt][nt][0]; v0.y = alpha * acc[mt][nt][1];
                v1.x = alpha * acc[mt][nt][2]; v1.y = alpha * acc[mt][nt][3];
            } else if (MODE == 1) {
                v0.x = __expf(alpha * acc[mt][nt][0]);
                v0.y = __expf(alpha * acc[mt][nt][1]);
                v1.x = __expf(alpha * acc[mt][nt][2]);
                v1.y = __expf(alpha * acc[mt][nt][3]);
            } else {
                v0.x = s0 * acc[mt][nt][0]; v0.y = s0 * acc[mt][nt][1];
                v1.x = s1 * acc[mt][nt][2]; v1.y = s1 * acc[mt][nt][3];
            }
            *reinterpret_cast<float2*>(&C[(size_t)r0 * N + col]) = v0;
            *reinterpret_cast<float2*>(&C[(size_t)r1 * N + col]) = v1;
        }
    }
}

// ---------------------------------------------------------------------------
// Batched QKV projection: grid (18, 32); blockIdx.x/6 selects Wq/Wk/Wv.
// 128x128 tile, 256 threads (8 warps 2x4, warp tile 64x32), 2 CTAs/SM.
// ---------------------------------------------------------------------------
__global__ void __launch_bounds__(256, 2)
proj_qkv(const float* __restrict__ A,
         const float* __restrict__ Wq, const float* __restrict__ Wk,
         const float* __restrict__ Wv,
         float* __restrict__ Qo, float* __restrict__ Ko, float* __restrict__ Vo)
{
    const int M = SEQ, N = DOUT, K = DIN;
    const int sel = blockIdx.x / 6;
    const float* B = (sel == 0) ? Wq : (sel == 1) ? Wk : Wv;
    float* C = (sel == 0) ? Qo : (sel == 1) ? Ko : Vo;

    __shared__ float As[2][128 * 16];
    __shared__ float Bs[2][128 * 16];

    const int tid  = threadIdx.x;
    const int lane = tid & 31;
    const int wid  = tid >> 5;
    const int bm = blockIdx.y * 128;
    const int bn = (blockIdx.x % 6) * 128;

    const int warp_m = wid & 1;
    const int warp_n = wid >> 1;
    const int m_base = warp_m * 64;
    const int n_base = warp_n * 32;

    const int a_row  = lane & 15;
    const int a_csel = (lane >> 4) & 1;
    const int b_row  = (lane & 7) + ((lane & 16) >> 1);
    const int b_csel = (lane >> 3) & 1;

    const uint32_t as_base0 = (uint32_t)__cvta_generic_to_shared(&As[0][0]);
    const uint32_t bs_base0 = (uint32_t)__cvta_generic_to_shared(&Bs[0][0]);
    const uint32_t buf_stride = 128 * 16 * 4;

    const int a_r0 = tid >> 2;
    const int a_c0 = tid & 3;
    const int a_r1 = (tid + 256) >> 2;
    const int bn_k0 = tid >> 7;
    const int bn_n0 = tid & 127;
    const int bn_k1 = (tid >> 7) + 2;

    float acc[4][4][4];
#pragma unroll
    for (int mt = 0; mt < 4; ++mt)
#pragma unroll
        for (int nt = 0; nt < 4; ++nt)
#pragma unroll
            for (int i = 0; i < 4; ++i) acc[mt][nt][i] = 0.0f;

    float4 pa0, pa1;
    float  pc0[4], pc1[4];

    auto ldg_tile = [&](int k0) {
        pa0 = *reinterpret_cast<const float4*>(&A[(size_t)(bm + a_r0) * K + k0 + a_c0 * 4]);
        pa1 = *reinterpret_cast<const float4*>(&A[(size_t)(bm + a_r1) * K + k0 + a_c0 * 4]);
#pragma unroll
        for (int j = 0; j < 4; ++j)
            pc0[j] = B[(size_t)(k0 + bn_k0 * 4 + j) * N + bn + bn_n0];
#pragma unroll
        for (int j = 0; j < 4; ++j)
            pc1[j] = B[(size_t)(k0 + bn_k1 * 4 + j) * N + bn + bn_n0];
    };

    auto sts_tile = [&](int b) {
        float4 t;
        t.x = __uint_as_float(f2tf32(pa0.x)); t.y = __uint_as_float(f2tf32(pa0.y));
        t.z = __uint_as_float(f2tf32(pa0.z)); t.w = __uint_as_float(f2tf32(pa0.w));
        *reinterpret_cast<float4*>(&As[b][sw16(a_r0, a_c0) * 4]) = t;
        t.x = __uint_as_float(f2tf32(pa1.x)); t.y = __uint_as_float(f2tf32(pa1.y));
        t.z = __uint_as_float(f2tf32(pa1.z)); t.w = __uint_as_float(f2tf32(pa1.w));
        *reinterpret_cast<float4*>(&As[b][sw16(a_r1, a_c0) * 4]) = t;
        t.x = __uint_as_float(f2tf32(pc0[0])); t.y = __uint_as_float(f2tf32(pc0[1]));
        t.z = __uint_as_float(f2tf32(pc0[2])); t.w = __uint_as_float(f2tf32(pc0[3]));
        *reinterpret_cast<float4*>(&Bs[b][sw16(bn_n0, bn_k0) * 4]) = t;
        t.x = __uint_as_float(f2tf32(pc1[0])); t.y = __uint_as_float(f2tf32(pc1[1]));
        t.z = __uint_as_float(f2tf32(pc1[2])); t.w = __uint_as_float(f2tf32(pc1[3]));
        *reinterpret_cast<float4*>(&Bs[b][sw16(bn_n0, bn_k1) * 4]) = t;
    };

    auto compute_tile = [&](int b) {
        const uint32_t as_b = as_base0 + (uint32_t)b * buf_stride;
        const uint32_t bs_b = bs_base0 + (uint32_t)b * buf_stride;
#pragma unroll
        for (int kk = 0; kk < 2; ++kk) {
            uint32_t af[4][4];
#pragma unroll
            for (int mt = 0; mt < 4; ++mt) {
                int m = m_base + mt * 16 + a_row;
                int c = 2 * kk + a_csel;
                ldsm4(af[mt], as_b + sw16(m, c) * 16);
            }
            uint32_t bf[2][4];
#pragma unroll
            for (int np = 0; np < 2; ++np) {
                int n = n_base + np * 16 + b_row;
                int c = 2 * kk + b_csel;
                ldsm4(bf[np], bs_b + sw16(n, c) * 16);
            }
#pragma unroll
            for (int mt = 0; mt < 4; ++mt)
#pragma unroll
                for (int nt = 0; nt < 4; ++nt)
                    mma_tf32(acc[mt][nt], af[mt],
                             bf[nt >> 1][(nt & 1) * 2],
                             bf[nt >> 1][(nt & 1) * 2 + 1]);
        }
    };

    ldg_tile(0);
    sts_tile(0);
    __syncthreads();

    const int niter = K / 16;
    int buf = 0;
    for (int it = 1; it < niter; ++it) {
        ldg_tile(it * 16);
        compute_tile(buf);
        sts_tile(buf ^ 1);
        __syncthreads();
        buf ^= 1;
    }
    compute_tile(buf);

    const int g = lane >> 2;
    const int tq = lane & 3;
#pragma unroll
    for (int mt = 0; mt < 4; ++mt) {
#pragma unroll
        for (int nt = 0; nt < 4; ++nt) {
            const int col = bn + n_base + nt * 8 + tq * 2;
            const int r0 = bm + m_base + mt * 16 + g;
            const int r1 = r0 + 8;
            float2 v0, v1;
            v0.x = acc[mt][nt][0]; v0.y = acc[mt][nt][1];
            v1.x = acc[mt][nt][2]; v1.y = acc[mt][nt][3];
            *reinterpret_cast<float2*>(&C[(size_t)r0 * N + col]) = v0;
            *reinterpret_cast<float2*>(&C[(size_t)r1 * N + col]) = v1;
        }
    }
}

// ---------------------------------------------------------------------------
// Row-sum reciprocal: inv[row] = 1 / sum(E[row, :]). Deterministic.
// ---------------------------------------------------------------------------
__global__ void __launch_bounds__(256)
rowinv_kernel(const float* __restrict__ E, float* __restrict__ inv)
{
    const int row = blockIdx.x;
    const int tid = threadIdx.x;
    const float* p = E + (size_t)row * SEQ;

    __shared__ float sm_red[8];

    float s = 0.0f;
#pragma unroll
    for (int it = 0; it < 4; ++it) {
        float4 t = *reinterpret_cast<const float4*>(&p[it * 1024 + tid * 4]);
        s += t.x + t.y + t.z + t.w;
    }
#pragma unroll
    for (int o = 16; o > 0; o >>= 1) s += __shfl_xor_sync(0xffffffffu, s, o);
    if ((tid & 31) == 0) sm_red[tid >> 5] = s;
    __syncthreads();
    if (tid == 0) {
        float ss = sm_red[0];
#pragma unroll
        for (int w = 1; w < 8; ++w) ss += sm_red[w];
        inv[row] = 1.0f / ss;
    }
}

// ---------------------------------------------------------------------------
extern "C" void kernel_launch(void* const* d_in, const int* in_sizes, int n_in,
                              void* d_out, int out_size)
{
    const float* x  = (const float*)d_in[0];
    const float* Wq = (const float*)d_in[1];
    const float* Wk = (const float*)d_in[2];
    const float* Wv = (const float*)d_in[3];
    float* out = (float*)d_out;

    float* Q;   cudaGetSymbolAddress((void**)&Q,   g_Q);
    float* K_;  cudaGetSymbolAddress((void**)&K_,  g_K);
    float* V;   cudaGetSymbolAddress((void**)&V,   g_V);
    float* E;   cudaGetSymbolAddress((void**)&E,   g_E);
    float* inv; cudaGetSymbolAddress((void**)&inv, g_inv);

    const float inv_sqrt_d = 0.036084391824351615f;  // 1/sqrt(768)

    dim3 grid_proj(18, SEQ / 128);           // batched Q,K,V
    dim3 grid_ss(SEQ / 128, SEQ / 128);      // (32, 32)
    dim3 grid_av(DOUT / 128, SEQ / 128);     // (6, 32)

    // Q, K, V projections in one launch (576 CTAs)
    proj_qkv<<<grid_proj, 256>>>(x, Wq, Wk, Wv, Q, K_, V);

    // E = exp(Q @ K^T / sqrt(d))   (fused exp epilogue; no max needed here)
    gemm_tf32_ww<1><<<grid_ss, 128>>>(Q, K_, E, SEQ, SEQ, DOUT, inv_sqrt_d, nullptr);

    // inv[row] = 1 / rowsum(E)
    rowinv_kernel<<<SEQ, 256>>>(E, inv);

    // out = diag(inv) * (E @ V)    (fused normalization at writeback)
    gemm_tf32_ww<2><<<grid_av, 128>>>(E, V, out, SEQ, DOUT, SEQ, 1.0f, inv);
}

// round 8
// speedup vs baseline: 1.4346x; 1.1116x over previous
#include <cuda_runtime.h>
#include <cstdint>

#define SEQ  4096
#define DIN  768
#define DOUT 768

// Scratch (allocation-free: __device__ globals).
__device__ float g_Q[SEQ * DOUT];
__device__ float g_K[SEQ * DOUT];
__device__ float g_V[SEQ * DOUT];
__device__ float g_E[(size_t)SEQ * SEQ];   // exp(scores)
__device__ float g_inv[SEQ];               // 1 / rowsum(E)
__device__ float g_P[3][SEQ * DOUT];       // AV split-K partials

// Split-K partition of K=4096 into 3 chunks (multiples of 16).
#define AV_K0 1376
#define AV_K1 1360
#define AV_K2 1360

// ---------------------------------------------------------------------------
// helpers
// ---------------------------------------------------------------------------
__device__ __forceinline__ uint32_t f2tf32(float f) {
    uint32_t r;
    asm("cvt.rna.tf32.f32 %0, %1;" : "=r"(r) : "f"(f));
    return r;
}

__device__ __forceinline__ void ldsm4(uint32_t r[4], uint32_t saddr) {
    asm volatile("ldmatrix.sync.aligned.m8n8.x4.shared.b16 {%0,%1,%2,%3}, [%4];"
                 : "=r"(r[0]), "=r"(r[1]), "=r"(r[2]), "=r"(r[3])
                 : "r"(saddr));
}

__device__ __forceinline__ void mma_tf32(float c[4],
                                         const uint32_t a[4],
                                         uint32_t b0, uint32_t b1) {
    asm volatile(
        "mma.sync.aligned.m16n8k8.row.col.f32.tf32.tf32.f32 "
        "{%0,%1,%2,%3}, {%4,%5,%6,%7}, {%8,%9}, {%0,%1,%2,%3};"
        : "+f"(c[0]), "+f"(c[1]), "+f"(c[2]), "+f"(c[3])
        : "r"(a[0]), "r"(a[1]), "r"(a[2]), "r"(a[3]), "r"(b0), "r"(b1));
}

// smem layout: tile [rows][16 k-floats] as 16B chunks, XOR swizzled.
__device__ __forceinline__ int sw16(int row, int c) {
    return row * 4 + (c ^ ((row >> 1) & 3));
}

// ---------------------------------------------------------------------------
// Wide-warp tf32 GEMM (QK^T + exp): block 128x128, BK=16, 128 threads
// (4 warps 2x2), warp tile 64x64, double-buffered smem, 2 CTAs/SM.
// B is [N,K] row-major (C = exp(alpha * A @ B^T)).
// ---------------------------------------------------------------------------
__global__ void __launch_bounds__(128, 2)
gemm_qk_exp(const float* __restrict__ A, const float* __restrict__ B,
            float* __restrict__ C, int M, int N, int K, float alpha)
{
    __shared__ float As[2][128 * 16];
    __shared__ float Bs[2][128 * 16];

    const int tid  = threadIdx.x;
    const int lane = tid & 31;
    const int wid  = tid >> 5;
    const int bm = blockIdx.y * 128;
    const int bn = blockIdx.x * 128;

    const int warp_m = wid & 1;
    const int warp_n = wid >> 1;
    const int m_base = warp_m * 64;
    const int n_base = warp_n * 64;

    const int a_row  = lane & 15;
    const int a_csel = (lane >> 4) & 1;
    const int b_row  = (lane & 7) + ((lane & 16) >> 1);
    const int b_csel = (lane >> 3) & 1;

    const uint32_t as_base0 = (uint32_t)__cvta_generic_to_shared(&As[0][0]);
    const uint32_t bs_base0 = (uint32_t)__cvta_generic_to_shared(&Bs[0][0]);
    const uint32_t buf_bytes = 128 * 16 * 4;

    int lr[4];
#pragma unroll
    for (int i = 0; i < 4; ++i) lr[i] = (tid + 128 * i) >> 2;
    const int lc = tid & 3;

    float acc[4][8][4];
#pragma unroll
    for (int mt = 0; mt < 4; ++mt)
#pragma unroll
        for (int nt = 0; nt < 8; ++nt)
#pragma unroll
            for (int i = 0; i < 4; ++i) acc[mt][nt][i] = 0.0f;

    float4 pa[4], pb[4];

    auto ldg_tile = [&](int k0) {
#pragma unroll
        for (int i = 0; i < 4; ++i)
            pa[i] = *reinterpret_cast<const float4*>(
                &A[(size_t)(bm + lr[i]) * K + k0 + lc * 4]);
#pragma unroll
        for (int i = 0; i < 4; ++i)
            pb[i] = *reinterpret_cast<const float4*>(
                &B[(size_t)(bn + lr[i]) * K + k0 + lc * 4]);
    };

    auto sts_tile = [&](int b) {
        float4 t;
#pragma unroll
        for (int i = 0; i < 4; ++i) {
            t.x = __uint_as_float(f2tf32(pa[i].x));
            t.y = __uint_as_float(f2tf32(pa[i].y));
            t.z = __uint_as_float(f2tf32(pa[i].z));
            t.w = __uint_as_float(f2tf32(pa[i].w));
            *reinterpret_cast<float4*>(&As[b][sw16(lr[i], lc) * 4]) = t;
        }
#pragma unroll
        for (int i = 0; i < 4; ++i) {
            t.x = __uint_as_float(f2tf32(pb[i].x));
            t.y = __uint_as_float(f2tf32(pb[i].y));
            t.z = __uint_as_float(f2tf32(pb[i].z));
            t.w = __uint_as_float(f2tf32(pb[i].w));
            *reinterpret_cast<float4*>(&Bs[b][sw16(lr[i], lc) * 4]) = t;
        }
    };

    auto compute_tile = [&](int b) {
        const uint32_t as_b = as_base0 + (uint32_t)b * buf_bytes;
        const uint32_t bs_b = bs_base0 + (uint32_t)b * buf_bytes;
#pragma unroll
        for (int kk = 0; kk < 2; ++kk) {
            uint32_t af[4][4];
#pragma unroll
            for (int mt = 0; mt < 4; ++mt) {
                int m = m_base + mt * 16 + a_row;
                int c = 2 * kk + a_csel;
                ldsm4(af[mt], as_b + sw16(m, c) * 16);
            }
            uint32_t bf[4][4];
#pragma unroll
            for (int np = 0; np < 4; ++np) {
                int n = n_base + np * 16 + b_row;
                int c = 2 * kk + b_csel;
                ldsm4(bf[np], bs_b + sw16(n, c) * 16);
            }
#pragma unroll
            for (int mt = 0; mt < 4; ++mt)
#pragma unroll
                for (int nt = 0; nt < 8; ++nt)
                    mma_tf32(acc[mt][nt], af[mt],
                             bf[nt >> 1][(nt & 1) * 2],
                             bf[nt >> 1][(nt & 1) * 2 + 1]);
        }
    };

    ldg_tile(0);
    sts_tile(0);
    __syncthreads();

    const int niter = K / 16;
    int buf = 0;
    for (int it = 1; it < niter; ++it) {
        ldg_tile(it * 16);
        compute_tile(buf);
        sts_tile(buf ^ 1);
        __syncthreads();
        buf ^= 1;
    }
    compute_tile(buf);

    const int g = lane >> 2;
    const int tq = lane & 3;
#pragma unroll
    for (int mt = 0; mt < 4; ++mt) {
        const int r0 = bm + m_base + mt * 16 + g;
        const int r1 = r0 + 8;
#pragma unroll
        for (int nt = 0; nt < 8; ++nt) {
            const int col = bn + n_base + nt * 8 + tq * 2;
            float2 v0, v1;
            v0.x = __expf(alpha * acc[mt][nt][0]);
            v0.y = __expf(alpha * acc[mt][nt][1]);
            v1.x = __expf(alpha * acc[mt][nt][2]);
            v1.y = __expf(alpha * acc[mt][nt][3]);
            *reinterpret_cast<float2*>(&C[(size_t)r0 * N + col]) = v0;
            *reinterpret_cast<float2*>(&C[(size_t)r1 * N + col]) = v1;
        }
    }
}

// ---------------------------------------------------------------------------
// AV split-K GEMM: P[z] = A[:, kRange(z)] @ B[kRange(z), :].
// Same validated mainloop; grid.z = 3 K-partitions (1376/1360/1360).
// B is [K,N] row-major. Partials written unscaled.
// ---------------------------------------------------------------------------
__global__ void __launch_bounds__(128, 2)
gemm_av_split(const float* __restrict__ A, const float* __restrict__ B,
              float* __restrict__ P, int M, int N, int K)
{
    __shared__ float As[2][128 * 16];
    __shared__ float Bs[2][128 * 16];

    const int tid  = threadIdx.x;
    const int lane = tid & 31;
    const int wid  = tid >> 5;
    const int bm = blockIdx.y * 128;
    const int bn = blockIdx.x * 128;
    const int z  = blockIdx.z;

    const int kBegin = (z == 0) ? 0 : AV_K0 + (z - 1) * AV_K1;
    const int kCount = (z == 0) ? AV_K0 : AV_K1;
    float* C = P + (size_t)z * SEQ * DOUT;

    const int warp_m = wid & 1;
    const int warp_n = wid >> 1;
    const int m_base = warp_m * 64;
    const int n_base = warp_n * 64;

    const int a_row  = lane & 15;
    const int a_csel = (lane >> 4) & 1;
    const int b_row  = (lane & 7) + ((lane & 16) >> 1);
    const int b_csel = (lane >> 3) & 1;

    const uint32_t as_base0 = (uint32_t)__cvta_generic_to_shared(&As[0][0]);
    const uint32_t bs_base0 = (uint32_t)__cvta_generic_to_shared(&Bs[0][0]);
    const uint32_t buf_bytes = 128 * 16 * 4;

    int lr[4];
#pragma unroll
    for (int i = 0; i < 4; ++i) lr[i] = (tid + 128 * i) >> 2;
    const int lc = tid & 3;

    float acc[4][8][4];
#pragma unroll
    for (int mt = 0; mt < 4; ++mt)
#pragma unroll
        for (int nt = 0; nt < 8; ++nt)
#pragma unroll
            for (int i = 0; i < 4; ++i) acc[mt][nt][i] = 0.0f;

    float4 pa[4];
    float  pc[4][4];

    auto ldg_tile = [&](int k0) {
#pragma unroll
        for (int i = 0; i < 4; ++i)
            pa[i] = *reinterpret_cast<const float4*>(
                &A[(size_t)(bm + lr[i]) * K + k0 + lc * 4]);
#pragma unroll
        for (int i = 0; i < 4; ++i)
#pragma unroll
            for (int j = 0; j < 4; ++j)
                pc[i][j] = B[(size_t)(k0 + i * 4 + j) * N + bn + tid];
    };

    auto sts_tile = [&](int b) {
        float4 t;
#pragma unroll
        for (int i = 0; i < 4; ++i) {
            t.x = __uint_as_float(f2tf32(pa[i].x));
            t.y = __uint_as_float(f2tf32(pa[i].y));
            t.z = __uint_as_float(f2tf32(pa[i].z));
            t.w = __uint_as_float(f2tf32(pa[i].w));
            *reinterpret_cast<float4*>(&As[b][sw16(lr[i], lc) * 4]) = t;
        }
#pragma unroll
        for (int i = 0; i < 4; ++i) {
            t.x = __uint_as_float(f2tf32(pc[i][0]));
            t.y = __uint_as_float(f2tf32(pc[i][1]));
            t.z = __uint_as_float(f2tf32(pc[i][2]));
            t.w = __uint_as_float(f2tf32(pc[i][3]));
            *reinterpret_cast<float4*>(&Bs[b][sw16(tid, i) * 4]) = t;
        }
    };

    auto compute_tile = [&](int b) {
        const uint32_t as_b = as_base0 + (uint32_t)b * buf_bytes;
        const uint32_t bs_b = bs_base0 + (uint32_t)b * buf_bytes;
#pragma unroll
        for (int kk = 0; kk < 2; ++kk) {
            uint32_t af[4][4];
#pragma unroll
            for (int mt = 0; mt < 4; ++mt) {
                int m = m_base + mt * 16 + a_row;
                int c = 2 * kk + a_csel;
                ldsm4(af[mt], as_b + sw16(m, c) * 16);
            }
            uint32_t bf[4][4];
#pragma unroll
            for (int np = 0; np < 4; ++np) {
                int n = n_base + np * 16 + b_row;
                int c = 2 * kk + b_csel;
                ldsm4(bf[np], bs_b + sw16(n, c) * 16);
            }
#pragma unroll
            for (int mt = 0; mt < 4; ++mt)
#pragma unroll
                for (int nt = 0; nt < 8; ++nt)
                    mma_tf32(acc[mt][nt], af[mt],
                             bf[nt >> 1][(nt & 1) * 2],
                             bf[nt >> 1][(nt & 1) * 2 + 1]);
        }
    };

    ldg_tile(kBegin);
    sts_tile(0);
    __syncthreads();

    const int niter = kCount / 16;
    int buf = 0;
    for (int it = 1; it < niter; ++it) {
        ldg_tile(kBegin + it * 16);
        compute_tile(buf);
        sts_tile(buf ^ 1);
        __syncthreads();
        buf ^= 1;
    }
    compute_tile(buf);

    const int g = lane >> 2;
    const int tq = lane & 3;
#pragma unroll
    for (int mt = 0; mt < 4; ++mt) {
        const int r0 = bm + m_base + mt * 16 + g;
        const int r1 = r0 + 8;
#pragma unroll
        for (int nt = 0; nt < 8; ++nt) {
            const int col = bn + n_base + nt * 8 + tq * 2;
            float2 v0, v1;
            v0.x = acc[mt][nt][0]; v0.y = acc[mt][nt][1];
            v1.x = acc[mt][nt][2]; v1.y = acc[mt][nt][3];
            *reinterpret_cast<float2*>(&C[(size_t)r0 * N + col]) = v0;
            *reinterpret_cast<float2*>(&C[(size_t)r1 * N + col]) = v1;
        }
    }
}

// ---------------------------------------------------------------------------
// Reduce partials + apply row normalization:
// out[r,c] = (P0[r,c] + P1[r,c] + P2[r,c]) * inv[r].  Deterministic order.
// ---------------------------------------------------------------------------
__global__ void __launch_bounds__(256)
reduce_av(const float* __restrict__ P, const float* __restrict__ inv,
          float* __restrict__ out)
{
    const size_t stride = (size_t)SEQ * DOUT;
    const size_t i4 = (size_t)blockIdx.x * 256 + threadIdx.x;   // float4 index
    const size_t base = i4 * 4;
    const int row = (int)(base / DOUT);
    const float s = inv[row];

    float4 a = *reinterpret_cast<const float4*>(&P[base]);
    float4 b = *reinterpret_cast<const float4*>(&P[stride + base]);
    float4 c = *reinterpret_cast<const float4*>(&P[2 * stride + base]);
    float4 o;
    o.x = (a.x + b.x + c.x) * s;
    o.y = (a.y + b.y + c.y) * s;
    o.z = (a.z + b.z + c.z) * s;
    o.w = (a.w + b.w + c.w) * s;
    *reinterpret_cast<float4*>(&out[base]) = o;
}

// ---------------------------------------------------------------------------
// Batched QKV projection: grid (18, 32); blockIdx.x/6 selects Wq/Wk/Wv.
// 128x128 tile, 256 threads (8 warps 2x4, warp tile 64x32), 2 CTAs/SM.
// ---------------------------------------------------------------------------
__global__ void __launch_bounds__(256, 2)
proj_qkv(const float* __restrict__ A,
         const float* __restrict__ Wq, const float* __restrict__ Wk,
         const float* __restrict__ Wv,
         float* __restrict__ Qo, float* __restrict__ Ko, float* __restrict__ Vo)
{
    const int M = SEQ, N = DOUT, K = DIN;
    const int sel = blockIdx.x / 6;
    const float* B = (sel == 0) ? Wq : (sel == 1) ? Wk : Wv;
    float* C = (sel == 0) ? Qo : (sel == 1) ? Ko : Vo;

    __shared__ float As[2][128 * 16];
    __shared__ float Bs[2][128 * 16];

    const int tid  = threadIdx.x;
    const int lane = tid & 31;
    const int wid  = tid >> 5;
    const int bm = blockIdx.y * 128;
    const int bn = (blockIdx.x % 6) * 128;

    const int warp_m = wid & 1;
    const int warp_n = wid >> 1;
    const int m_base = warp_m * 64;
    const int n_base = warp_n * 32;

    const int a_row  = lane & 15;
    const int a_csel = (lane >> 4) & 1;
    const int b_row  = (lane & 7) + ((lane & 16) >> 1);
    const int b_csel = (lane >> 3) & 1;

    const uint32_t as_base0 = (uint32_t)__cvta_generic_to_shared(&As[0][0]);
    const uint32_t bs_base0 = (uint32_t)__cvta_generic_to_shared(&Bs[0][0]);
    const uint32_t buf_stride = 128 * 16 * 4;

    const int a_r0 = tid >> 2;
    const int a_c0 = tid & 3;
    const int a_r1 = (tid + 256) >> 2;
    const int bn_k0 = tid >> 7;
    const int bn_n0 = tid & 127;
    const int bn_k1 = (tid >> 7) + 2;

    float acc[4][4][4];
#pragma unroll
    for (int mt = 0; mt < 4; ++mt)
#pragma unroll
        for (int nt = 0; nt < 4; ++nt)
#pragma unroll
            for (int i = 0; i < 4; ++i) acc[mt][nt][i] = 0.0f;

    float4 pa0, pa1;
    float  pc0[4], pc1[4];

    auto ldg_tile = [&](int k0) {
        pa0 = *reinterpret_cast<const float4*>(&A[(size_t)(bm + a_r0) * K + k0 + a_c0 * 4]);
        pa1 = *reinterpret_cast<const float4*>(&A[(size_t)(bm + a_r1) * K + k0 + a_c0 * 4]);
#pragma unroll
        for (int j = 0; j < 4; ++j)
            pc0[j] = B[(size_t)(k0 + bn_k0 * 4 + j) * N + bn + bn_n0];
#pragma unroll
        for (int j = 0; j < 4; ++j)
            pc1[j] = B[(size_t)(k0 + bn_k1 * 4 + j) * N + bn + bn_n0];
    };

    auto sts_tile = [&](int b) {
        float4 t;
        t.x = __uint_as_float(f2tf32(pa0.x)); t.y = __uint_as_float(f2tf32(pa0.y));
        t.z = __uint_as_float(f2tf32(pa0.z)); t.w = __uint_as_float(f2tf32(pa0.w));
        *reinterpret_cast<float4*>(&As[b][sw16(a_r0, a_c0) * 4]) = t;
        t.x = __uint_as_float(f2tf32(pa1.x)); t.y = __uint_as_float(f2tf32(pa1.y));
        t.z = __uint_as_float(f2tf32(pa1.z)); t.w = __uint_as_float(f2tf32(pa1.w));
        *reinterpret_cast<float4*>(&As[b][sw16(a_r1, a_c0) * 4]) = t;
        t.x = __uint_as_float(f2tf32(pc0[0])); t.y = __uint_as_float(f2tf32(pc0[1]));
        t.z = __uint_as_float(f2tf32(pc0[2])); t.w = __uint_as_float(f2tf32(pc0[3]));
        *reinterpret_cast<float4*>(&Bs[b][sw16(bn_n0, bn_k0) * 4]) = t;
        t.x = __uint_as_float(f2tf32(pc1[0])); t.y = __uint_as_float(f2tf32(pc1[1]));
        t.z = __uint_as_float(f2tf32(pc1[2])); t.w = __uint_as_float(f2tf32(pc1[3]));
        *reinterpret_cast<float4*>(&Bs[b][sw16(bn_n0, bn_k1) * 4]) = t;
    };

    auto compute_tile = [&](int b) {
        const uint32_t as_b = as_base0 + (uint32_t)b * buf_stride;
        const uint32_t bs_b = bs_base0 + (uint32_t)b * buf_stride;
#pragma unroll
        for (int kk = 0; kk < 2; ++kk) {
            uint32_t af[4][4];
#pragma unroll
            for (int mt = 0; mt < 4; ++mt) {
                int m = m_base + mt * 16 + a_row;
                int c = 2 * kk + a_csel;
                ldsm4(af[mt], as_b + sw16(m, c) * 16);
            }
            uint32_t bf[2][4];
#pragma unroll
            for (int np = 0; np < 2; ++np) {
                int n = n_base + np * 16 + b_row;
                int c = 2 * kk + b_csel;
                ldsm4(bf[np], bs_b + sw16(n, c) * 16);
            }
#pragma unroll
            for (int mt = 0; mt < 4; ++mt)
#pragma unroll
                for (int nt = 0; nt < 4; ++nt)
                    mma_tf32(acc[mt][nt], af[mt],
                             bf[nt >> 1][(nt & 1) * 2],
                             bf[nt >> 1][(nt & 1) * 2 + 1]);
        }
    };

    ldg_tile(0);
    sts_tile(0);
    __syncthreads();

    const int niter = K / 16;
    int buf = 0;
    for (int it = 1; it < niter; ++it) {
        ldg_tile(it * 16);
        compute_tile(buf);
        sts_tile(buf ^ 1);
        __syncthreads();
        buf ^= 1;
    }
    compute_tile(buf);

    const int g = lane >> 2;
    const int tq = lane & 3;
#pragma unroll
    for (int mt = 0; mt < 4; ++mt) {
#pragma unroll
        for (int nt = 0; nt < 4; ++nt) {
            const int col = bn + n_base + nt * 8 + tq * 2;
            const int r0 = bm + m_base + mt * 16 + g;
            const int r1 = r0 + 8;
            float2 v0, v1;
            v0.x = acc[mt][nt][0]; v0.y = acc[mt][nt][1];
            v1.x = acc[mt][nt][2]; v1.y = acc[mt][nt][3];
            *reinterpret_cast<float2*>(&C[(size_t)r0 * N + col]) = v0;
            *reinterpret_cast<float2*>(&C[(size_t)r1 * N + col]) = v1;
        }
    }
}

// ---------------------------------------------------------------------------
// Row-sum reciprocal: inv[row] = 1 / sum(E[row, :]). Deterministic.
// ---------------------------------------------------------------------------
__global__ void __launch_bounds__(256)
rowinv_kernel(const float* __restrict__ E, float* __restrict__ inv)
{
    const int row = blockIdx.x;
    const int tid = threadIdx.x;
    const float* p = E + (size_t)row * SEQ;

    __shared__ float sm_red[8];

    float s = 0.0f;
#pragma unroll
    for (int it = 0; it < 4; ++it) {
        float4 t = *reinterpret_cast<const float4*>(&p[it * 1024 + tid * 4]);
        s += t.x + t.y + t.z + t.w;
    }
#pragma unroll
    for (int o = 16; o > 0; o >>= 1) s += __shfl_xor_sync(0xffffffffu, s, o);
    if ((tid & 31) == 0) sm_red[tid >> 5] = s;
    __syncthreads();
    if (tid == 0) {
        float ss = sm_red[0];
#pragma unroll
        for (int w = 1; w < 8; ++w) ss += sm_red[w];
        inv[row] = 1.0f / ss;
    }
}

// ---------------------------------------------------------------------------
extern "C" void kernel_launch(void* const* d_in, const int* in_sizes, int n_in,
                              void* d_out, int out_size)
{
    const float* x  = (const float*)d_in[0];
    const float* Wq = (const float*)d_in[1];
    const float* Wk = (const float*)d_in[2];
    const float* Wv = (const float*)d_in[3];
    float* out = (float*)d_out;

    float* Q;   cudaGetSymbolAddress((void**)&Q,   g_Q);
    float* K_;  cudaGetSymbolAddress((void**)&K_,  g_K);
    float* V;   cudaGetSymbolAddress((void**)&V,   g_V);
    float* E;   cudaGetSymbolAddress((void**)&E,   g_E);
    float* inv; cudaGetSymbolAddress((void**)&inv, g_inv);
    float* P;   cudaGetSymbolAddress((void**)&P,   g_P);

    const float inv_sqrt_d = 0.036084391824351615f;  // 1/sqrt(768)

    dim3 grid_proj(18, SEQ / 128);            // batched Q,K,V
    dim3 grid_ss(SEQ / 128, SEQ / 128);       // (32, 32)
    dim3 grid_av(DOUT / 128, SEQ / 128, 3);   // (6, 32, 3) split-K

    // Q, K, V projections in one launch (576 CTAs)
    proj_qkv<<<grid_proj, 256>>>(x, Wq, Wk, Wv, Q, K_, V);

    // E = exp(Q @ K^T / sqrt(d))
    gemm_qk_exp<<<grid_ss, 128>>>(Q, K_, E, SEQ, SEQ, DOUT, inv_sqrt_d);

    // inv[row] = 1 / rowsum(E)
    rowinv_kernel<<<SEQ, 256>>>(E, inv);

    // P[z] = E[:, Kz] @ V[Kz, :]   (split-K=3, 576 CTAs)
    gemm_av_split<<<grid_av, 128>>>(E, V, P, SEQ, DOUT, SEQ);

    // out = (P0 + P1 + P2) * inv[row]
    reduce_av<<<(SEQ * DOUT) / (256 * 4), 256>>>(P, inv, out);
}